// round 2
// baseline (speedup 1.0000x reference)
#include <cuda_runtime.h>
#include <cuda_bf16.h>
#include <cstdint>
#include <math.h>

#define N_ROWS 4096
#define KDIM   1024
#define VDIM   32000
#define BM 128
#define BN 128
#define BK 32
#define NVT (VDIM/BN)     // 250 v-tiles
#define NRT (N_ROWS/BM)   // 32 row-tiles
#define NKT (KDIM/BK)     // 32 k-iters
#define IGN (-100)

// ---- device-global scratch (no dynamic allocation allowed) ----
__device__ __nv_bfloat16 g_Xb[N_ROWS*KDIM];     // 8 MB
__device__ __nv_bfloat16 g_Wb[KDIM*VDIM];       // 65.5 MB
__device__ float g_pm[NVT*N_ROWS];              // per-(vtile,row) max
__device__ float g_ps[NVT*N_ROWS];              // per-(vtile,row) sumexp
__device__ float g_tl[N_ROWS];                  // target logits
__device__ float g_bp[32];                      // block partial sums

// ---- shared memory layout (bytes). A pitch 40 halves, B pitch 136 halves
//      (padded for conflict-free ldmatrix). Total 40448 < 48KB default. ----
#define A0_OFF 0
#define A1_OFF 10240
#define B0_OFF 20480
#define B1_OFF 29184
#define RM_OFF 37888
#define RS_OFF 38912
#define TG_OFF 39936
#define SMEM_BYTES 40448
#define APITCH 40
#define BPITCH 136

__device__ __forceinline__ void cp16(uint32_t dst, const void* src){
    asm volatile("cp.async.cg.shared.global [%0], [%1], 16;" :: "r"(dst), "l"(src));
}
__device__ __forceinline__ void cp_commit(){ asm volatile("cp.async.commit_group;"); }

// ============================================================
// Kernel 1: fp32 -> bf16 conversion of W and x; zero target-logit scratch
// ============================================================
__global__ void __launch_bounds__(256) conv_kernel(const float4* __restrict__ x4,
                                                   const float4* __restrict__ w4){
    int idx = blockIdx.x*blockDim.x + threadIdx.x;
    int stride = gridDim.x*blockDim.x;
    __nv_bfloat162* wo = reinterpret_cast<__nv_bfloat162*>(g_Wb);
    const int W4 = KDIM*VDIM/4;
    for (int i = idx; i < W4; i += stride){
        float4 v = w4[i];
        wo[2*i]   = __floats2bfloat162_rn(v.x, v.y);
        wo[2*i+1] = __floats2bfloat162_rn(v.z, v.w);
    }
    __nv_bfloat162* xo = reinterpret_cast<__nv_bfloat162*>(g_Xb);
    const int X4 = N_ROWS*KDIM/4;
    for (int i = idx; i < X4; i += stride){
        float4 v = x4[i];
        xo[2*i]   = __floats2bfloat162_rn(v.x, v.y);
        xo[2*i+1] = __floats2bfloat162_rn(v.z, v.w);
    }
    if (idx < N_ROWS) g_tl[idx] = 0.f;
}

// ============================================================
// Kernel 2: tiled bf16 GEMM (mma.sync m16n8k16) + fused online-softmax
// epilogue. grid = (250 vtiles, 32 rowtiles). 8 warps: 4 (m) x 2 (n);
// warp tile 32x64. cp.async double-buffered K loop (32 iters of BK=32).
// ============================================================
// A tile: 128 rows x 32 halves = 8KB = 512 cp16 ops (2 per thread).
// B tile: 32 rows x 128 halves = 8KB = 512 cp16 ops (2 per thread).
#define LOAD_TILES(kt, abuf_off, bbuf_off) do {                                        \
    int k0_ = (kt)*BK;                                                                  \
    _Pragma("unroll")                                                                   \
    for (int j_=0; j_<2; j_++){                                                         \
        int i_ = tid + j_*256; int row_ = i_>>2, seg_ = i_&3;                           \
        cp16(sbase + (abuf_off) + (uint32_t)((row_*APITCH + seg_*8)*2),                 \
             g_Xb + (m0+row_)*KDIM + k0_ + seg_*8);                                     \
    }                                                                                   \
    _Pragma("unroll")                                                                   \
    for (int j_=0; j_<2; j_++){                                                         \
        int i_ = tid + j_*256; int kr_ = i_>>4, seg_ = i_&15;                           \
        cp16(sbase + (bbuf_off) + (uint32_t)((kr_*BPITCH + seg_*8)*2),                  \
             g_Wb + (k0_+kr_)*VDIM + v0 + seg_*8); }                                    \
    cp_commit();                                                                        \
} while(0)

#define COMPUTE_TILE(abuf_off, bbuf_off) do {                                           \
    const int r16_ = lane & 15, cb_ = lane >> 4;                                        \
    _Pragma("unroll")                                                                   \
    for (int kk_=0; kk_<2; kk_++){                                                      \
        uint32_t a_[2][4];                                                              \
        _Pragma("unroll")                                                               \
        for (int mi_=0; mi_<2; mi_++){                                                  \
            uint32_t ad_ = sbase + (abuf_off) +                                         \
                (uint32_t)(((wm*32 + mi_*16 + r16_)*APITCH + kk_*16 + cb_*8)*2);        \
            asm volatile("ldmatrix.sync.aligned.m8n8.x4.shared.b16 {%0,%1,%2,%3}, [%4];"\
                : "=r"(a_[mi_][0]),"=r"(a_[mi_][1]),"=r"(a_[mi_][2]),"=r"(a_[mi_][3])   \
                : "r"(ad_));                                                            \
        }                                                                               \
        uint32_t b_[8][2];                                                              \
        _Pragma("unroll")                                                               \
        for (int nj_=0; nj_<4; nj_++){                                                  \
            uint32_t bd_ = sbase + (bbuf_off) +                                         \
                (uint32_t)(((kk_*16 + r16_)*BPITCH + wn*64 + nj_*16 + cb_*8)*2);        \
            uint32_t t0_,t1_,t2_,t3_;                                                   \
            asm volatile("ldmatrix.sync.aligned.m8n8.x4.trans.shared.b16 {%0,%1,%2,%3}, [%4];" \
                : "=r"(t0_),"=r"(t1_),"=r"(t2_),"=r"(t3_) : "r"(bd_));                  \
            b_[2*nj_][0]=t0_;  b_[2*nj_][1]=t1_;                                        \
            b_[2*nj_+1][0]=t2_; b_[2*nj_+1][1]=t3_;                                     \
        }                                                                               \
        _Pragma("unroll")                                                               \
        for (int mi_=0; mi_<2; mi_++){                                                  \
            _Pragma("unroll")                                                           \
            for (int ni_=0; ni_<8; ni_++){                                              \
                asm volatile("mma.sync.aligned.m16n8k16.row.col.f32.bf16.bf16.f32 "     \
                    "{%0,%1,%2,%3}, {%4,%5,%6,%7}, {%8,%9}, {%0,%1,%2,%3};"             \
                    : "+f"(c[mi_][ni_][0]),"+f"(c[mi_][ni_][1]),                        \
                      "+f"(c[mi_][ni_][2]),"+f"(c[mi_][ni_][3])                         \
                    : "r"(a_[mi_][0]),"r"(a_[mi_][1]),"r"(a_[mi_][2]),"r"(a_[mi_][3]),  \
                      "r"(b_[ni_][0]),"r"(b_[ni_][1]));                                 \
            }                                                                           \
        }                                                                               \
    }                                                                                   \
} while(0)

__global__ void __launch_bounds__(256,1) gemm_kernel(const int* __restrict__ target){
    extern __shared__ char smem[];
    const int tid = threadIdx.x, lane = tid & 31, wid = tid >> 5;
    const int wm = wid >> 1, wn = wid & 1;
    const int vt = blockIdx.x, rt = blockIdx.y;
    const int v0 = vt*BN, m0 = rt*BM;

    int* stg = reinterpret_cast<int*>(smem + TG_OFF);
    if (tid < BM) stg[tid] = target[m0 + tid];

    const uint32_t sbase = (uint32_t)__cvta_generic_to_shared(smem);

    float c[2][8][4];
    #pragma unroll
    for (int mi=0; mi<2; mi++)
        #pragma unroll
        for (int ni=0; ni<8; ni++)
            #pragma unroll
            for (int j=0; j<4; j++) c[mi][ni][j] = 0.f;

    LOAD_TILES(0, A0_OFF, B0_OFF);

    #pragma unroll 1
    for (int kt = 0; kt < NKT; kt++){
        int cur = kt & 1;
        if (kt + 1 < NKT){
            if (cur == 0) LOAD_TILES(kt+1, A1_OFF, B1_OFF);
            else          LOAD_TILES(kt+1, A0_OFF, B0_OFF);
            asm volatile("cp.async.wait_group 1;" ::: "memory");
        } else {
            asm volatile("cp.async.wait_group 0;" ::: "memory");
        }
        __syncthreads();
        if (cur == 0) COMPUTE_TILE(A0_OFF, B0_OFF);
        else          COMPUTE_TILE(A1_OFF, B1_OFF);
        __syncthreads();
    }

    // ---- fused epilogue: per-row tile max + sumexp + target-logit capture ----
    // C fragment: c0=(g,2t), c1=(g,2t+1), c2=(g+8,2t), c3=(g+8,2t+1); g=lane/4, t=lane%4
    float* rm = reinterpret_cast<float*>(smem + RM_OFF);  // [128][2]
    float* rs = reinterpret_cast<float*>(smem + RS_OFF);  // [128][2]
    const int g = lane >> 2, tig = lane & 3;

    #pragma unroll
    for (int mi=0; mi<2; mi++){
        #pragma unroll
        for (int h=0; h<2; h++){
            float m = -INFINITY;
            #pragma unroll
            for (int ni=0; ni<8; ni++){
                m = fmaxf(m, c[mi][ni][2*h]);
                m = fmaxf(m, c[mi][ni][2*h+1]);
            }
            m = fmaxf(m, __shfl_xor_sync(0xffffffffu, m, 1));
            m = fmaxf(m, __shfl_xor_sync(0xffffffffu, m, 2));
            int row = wm*32 + mi*16 + h*8 + g;
            if (tig == 0) rm[row*2 + wn] = m;
        }
    }
    __syncthreads();
    #pragma unroll
    for (int mi=0; mi<2; mi++){
        #pragma unroll
        for (int h=0; h<2; h++){
            int row = wm*32 + mi*16 + h*8 + g;
            float mrow = fmaxf(rm[row*2], rm[row*2+1]);
            int tc = stg[row] - v0;     // target col within this v-tile (or out of range)
            float s = 0.f;
            #pragma unroll
            for (int ni=0; ni<8; ni++){
                float va = c[mi][ni][2*h], vb = c[mi][ni][2*h+1];
                s += __expf(va - mrow) + __expf(vb - mrow);
                int col = wn*64 + ni*8 + 2*tig;
                if (col   == tc) g_tl[m0+row] = va;
                if (col+1 == tc) g_tl[m0+row] = vb;
            }
            s += __shfl_xor_sync(0xffffffffu, s, 1);
            s += __shfl_xor_sync(0xffffffffu, s, 2);
            if (tig == 0) rs[row*2 + wn] = s;
        }
    }
    __syncthreads();
    if (wn == 0 && tig == 0){
        #pragma unroll
        for (int mi=0; mi<2; mi++){
            #pragma unroll
            for (int h=0; h<2; h++){
                int row = wm*32 + mi*16 + h*8 + g;
                float mrow = fmaxf(rm[row*2], rm[row*2+1]);
                g_pm[vt*N_ROWS + m0 + row] = mrow;
                g_ps[vt*N_ROWS + m0 + row] = rs[row*2] + rs[row*2+1];
            }
        }
    }
}

// ============================================================
// Kernel 3: split-LSE combine over 250 v-tiles per row + block partial sums
// ============================================================
__global__ void __launch_bounds__(256) combine_kernel(const int* __restrict__ target){
    int row = blockIdx.x*256 + threadIdx.x;
    float m = -INFINITY;
    for (int i = 0; i < NVT; i++) m = fmaxf(m, g_pm[i*N_ROWS + row]);
    float s = 0.f;
    for (int i = 0; i < NVT; i++) s += g_ps[i*N_ROWS + row] * __expf(g_pm[i*N_ROWS + row] - m);
    float lse = m + logf(s);
    int t = target[row];
    float valid = (t != IGN) ? 1.f : 0.f;
    float loss = (lse - g_tl[row]) * valid;
    float lsev = lse * valid;

    __shared__ float s1[256], s2[256];
    s1[threadIdx.x] = loss;
    s2[threadIdx.x] = lsev;
    __syncthreads();
    for (int off = 128; off > 0; off >>= 1){
        if (threadIdx.x < off){
            s1[threadIdx.x] += s1[threadIdx.x + off];
            s2[threadIdx.x] += s2[threadIdx.x + off];
        }
        __syncthreads();
    }
    if (threadIdx.x == 0){
        g_bp[blockIdx.x*2]   = s1[0];
        g_bp[blockIdx.x*2+1] = s2[0];
    }
}

// Kernel 4: deterministic final reduction of 16 block partials -> 2 scalars
__global__ void final_kernel(float* __restrict__ out){
    if (threadIdx.x == 0 && blockIdx.x == 0){
        float a = 0.f, b = 0.f;
        for (int i = 0; i < 16; i++){ a += g_bp[2*i]; b += g_bp[2*i+1]; }
        out[0] = a;   // sum of losses
        out[1] = b;   // sum of masked lse
    }
}

// ============================================================
extern "C" void kernel_launch(void* const* d_in, const int* in_sizes, int n_in,
                              void* d_out, int out_size){
    const float* x      = (const float*)d_in[0];  // [4096,1024] fp32
    const float* w      = (const float*)d_in[1];  // [1024,32000] fp32
    const int*   target = (const int*)d_in[2];    // [4096] int32
    float* out = (float*)d_out;

    conv_kernel<<<1024, 256>>>((const float4*)x, (const float4*)w);
    dim3 grid(NVT, NRT);
    gemm_kernel<<<grid, 256, SMEM_BYTES>>>(target);
    combine_kernel<<<16, 256>>>(target);
    final_kernel<<<1, 32>>>(out);
}

// round 4
// speedup vs baseline: 1.4773x; 1.4773x over previous
#include <cuda_runtime.h>
#include <cuda_bf16.h>
#include <cstdint>
#include <math.h>

#define N_ROWS 4096
#define KDIM   1024
#define VDIM   32000
#define BM 128
#define BN 256
#define BK 32
#define NVT (VDIM/BN)     // 125 v-tiles
#define NRT (N_ROWS/BM)   // 32 row-tiles
#define NKT (KDIM/BK)     // 32 k-iters
#define IGN (-100)

// ---- device-global scratch ----
__device__ __nv_bfloat16 g_Xb[N_ROWS*KDIM];     // 8 MB
__device__ __nv_bfloat16 g_Wb[KDIM*VDIM];       // 65.5 MB  [k][v]
__device__ float g_pm[NVT*N_ROWS];
__device__ float g_ps[NVT*N_ROWS];
__device__ float g_tl[N_ROWS];
__device__ float g_bp[32];

// ---- smem layout (bytes): 3-stage A (10240 ea) + 3-stage B (16896 ea) ----
#define APITCH 40           // halves per A row (32 + 8 pad)
#define BPITCH 264          // halves per B row (256 + 8 pad)
#define A_ST 10240
#define B_ST 16896
#define A_OFF(s) ((s)*A_ST)
#define B_OFF(s) (30720 + (s)*B_ST)
#define RM_OFF 81408
#define RS_OFF 83456
#define TG_OFF 85504
#define SMEM_BYTES 86016

__device__ __forceinline__ void cp16(uint32_t dst, const void* src){
    asm volatile("cp.async.cg.shared.global [%0], [%1], 16;" :: "r"(dst), "l"(src));
}
__device__ __forceinline__ void cp_commit(){ asm volatile("cp.async.commit_group;"); }

// ============================================================
// Kernel 1: fp32 -> bf16 conversion of W and x; zero target-logit scratch
// ============================================================
__global__ void __launch_bounds__(256) conv_kernel(const float4* __restrict__ x4,
                                                   const float4* __restrict__ w4){
    int idx = blockIdx.x*blockDim.x + threadIdx.x;
    int stride = gridDim.x*blockDim.x;
    __nv_bfloat162* wo = reinterpret_cast<__nv_bfloat162*>(g_Wb);
    const int W4 = KDIM*VDIM/4;
    for (int i = idx; i < W4; i += stride){
        float4 v = w4[i];
        wo[2*i]   = __floats2bfloat162_rn(v.x, v.y);
        wo[2*i+1] = __floats2bfloat162_rn(v.z, v.w);
    }
    __nv_bfloat162* xo = reinterpret_cast<__nv_bfloat162*>(g_Xb);
    const int X4 = N_ROWS*KDIM/4;
    for (int i = idx; i < X4; i += stride){
        float4 v = x4[i];
        xo[2*i]   = __floats2bfloat162_rn(v.x, v.y);
        xo[2*i+1] = __floats2bfloat162_rn(v.z, v.w);
    }
    if (idx < N_ROWS) g_tl[idx] = 0.f;
}

// ============================================================
// Kernel 2: 128x256 tiled bf16 GEMM (mma.sync m16n8k16) + fused softmax.
// 8 warps = 2(m) x 4(n), warp tile 64x64. 3-stage cp.async pipeline,
// one __syncthreads + one wait_group per K-iteration.
// ============================================================
// A tile: 128 rows x 32 halves = 512 cp16 (2/thread)
// B tile: 32 rows x 256 halves = 1024 cp16 (4/thread)
#define LOAD_TILES(kt, s) do {                                              \
    int k0_ = (kt)*BK;                                                      \
    _Pragma("unroll")                                                       \
    for (int j_=0; j_<2; j_++){                                             \
        int i_ = tid + j_*256; int row_ = i_>>2, seg_ = i_&3;               \
        cp16(sbase + A_OFF(s) + (uint32_t)((row_*APITCH + seg_*8)*2),       \
             g_Xb + (size_t)(m0+row_)*KDIM + k0_ + seg_*8);                 \
    }                                                                       \
    _Pragma("unroll")                                                       \
    for (int j_=0; j_<4; j_++){                                             \
        int i_ = tid + j_*256; int kr_ = i_>>5, seg_ = i_&31;               \
        cp16(sbase + B_OFF(s) + (uint32_t)((kr_*BPITCH + seg_*8)*2),        \
             g_Wb + (size_t)(k0_+kr_)*VDIM + v0 + seg_*8);                  \
    }                                                                       \
} while(0)

#define COMPUTE_TILE(s) do {                                                            \
    const int r16_ = lane & 15, cb_ = lane >> 4;                                        \
    _Pragma("unroll")                                                                   \
    for (int kk_=0; kk_<2; kk_++){                                                      \
        uint32_t a_[4][4];                                                              \
        _Pragma("unroll")                                                               \
        for (int mi_=0; mi_<4; mi_++){                                                  \
            uint32_t ad_ = sbase + A_OFF(s) +                                           \
                (uint32_t)(((wm*64 + mi_*16 + r16_)*APITCH + kk_*16 + cb_*8)*2);        \
            asm volatile("ldmatrix.sync.aligned.m8n8.x4.shared.b16 {%0,%1,%2,%3}, [%4];"\
                : "=r"(a_[mi_][0]),"=r"(a_[mi_][1]),"=r"(a_[mi_][2]),"=r"(a_[mi_][3])   \
                : "r"(ad_));                                                            \
        }                                                                               \
        uint32_t b_[8][2];                                                              \
        _Pragma("unroll")                                                               \
        for (int nj_=0; nj_<4; nj_++){                                                  \
            uint32_t bd_ = sbase + B_OFF(s) +                                           \
                (uint32_t)(((kk_*16 + r16_)*BPITCH + wn*64 + nj_*16 + cb_*8)*2);        \
            uint32_t t0_,t1_,t2_,t3_;                                                   \
            asm volatile("ldmatrix.sync.aligned.m8n8.x4.trans.shared.b16 {%0,%1,%2,%3}, [%4];" \
                : "=r"(t0_),"=r"(t1_),"=r"(t2_),"=r"(t3_) : "r"(bd_));                  \
            b_[2*nj_][0]=t0_;  b_[2*nj_][1]=t1_;                                        \
            b_[2*nj_+1][0]=t2_; b_[2*nj_+1][1]=t3_;                                     \
        }                                                                               \
        _Pragma("unroll")                                                               \
        for (int mi_=0; mi_<4; mi_++){                                                  \
            _Pragma("unroll")                                                           \
            for (int ni_=0; ni_<8; ni_++){                                              \
                asm volatile("mma.sync.aligned.m16n8k16.row.col.f32.bf16.bf16.f32 "     \
                    "{%0,%1,%2,%3}, {%4,%5,%6,%7}, {%8,%9}, {%0,%1,%2,%3};"             \
                    : "+f"(c[mi_][ni_][0]),"+f"(c[mi_][ni_][1]),                        \
                      "+f"(c[mi_][ni_][2]),"+f"(c[mi_][ni_][3])                         \
                    : "r"(a_[mi_][0]),"r"(a_[mi_][1]),"r"(a_[mi_][2]),"r"(a_[mi_][3]),  \
                      "r"(b_[ni_][0]),"r"(b_[ni_][1]));                                 \
            }                                                                           \
        }                                                                               \
    }                                                                                   \
} while(0)

__global__ void __launch_bounds__(256,1) gemm_kernel(const int* __restrict__ target){
    extern __shared__ char smem[];
    const int tid = threadIdx.x, lane = tid & 31, wid = tid >> 5;
    const int wm = wid >> 2, wn = wid & 3;
    const int vt = blockIdx.x, rt = blockIdx.y;
    const int v0 = vt*BN, m0 = rt*BM;

    int* stg = reinterpret_cast<int*>(smem + TG_OFF);
    if (tid < BM) stg[tid] = target[m0 + tid];

    const uint32_t sbase = (uint32_t)__cvta_generic_to_shared(smem);

    float c[4][8][4];
    #pragma unroll
    for (int mi=0; mi<4; mi++)
        #pragma unroll
        for (int ni=0; ni<8; ni++)
            #pragma unroll
            for (int j=0; j<4; j++) c[mi][ni][j] = 0.f;

    LOAD_TILES(0, 0); cp_commit();
    LOAD_TILES(1, 1); cp_commit();
    asm volatile("cp.async.wait_group 1;" ::: "memory");
    __syncthreads();

    #pragma unroll 1
    for (int kt = 0; kt < NKT; kt++){
        COMPUTE_TILE(kt % 3);
        if (kt + 2 < NKT) LOAD_TILES(kt+2, (kt+2) % 3);
        cp_commit();
        asm volatile("cp.async.wait_group 1;" ::: "memory");
        __syncthreads();
    }

    // ---- fused epilogue: per-row max + sumexp + target-logit capture ----
    // C fragment rows: row = wm*64 + mi*16 + h*8 + g; cols: wn*64 + ni*8 + 2*tig + {0,1}
    float* rm = reinterpret_cast<float*>(smem + RM_OFF);  // [128][4]
    float* rs = reinterpret_cast<float*>(smem + RS_OFF);  // [128][4]
    const int g = lane >> 2, tig = lane & 3;

    #pragma unroll
    for (int mi=0; mi<4; mi++){
        #pragma unroll
        for (int h=0; h<2; h++){
            float m = -INFINITY;
            #pragma unroll
            for (int ni=0; ni<8; ni++){
                m = fmaxf(m, c[mi][ni][2*h]);
                m = fmaxf(m, c[mi][ni][2*h+1]);
            }
            m = fmaxf(m, __shfl_xor_sync(0xffffffffu, m, 1));
            m = fmaxf(m, __shfl_xor_sync(0xffffffffu, m, 2));
            int row = wm*64 + mi*16 + h*8 + g;
            if (tig == 0) rm[row*4 + wn] = m;
        }
    }
    __syncthreads();
    #pragma unroll
    for (int mi=0; mi<4; mi++){
        #pragma unroll
        for (int h=0; h<2; h++){
            int row = wm*64 + mi*16 + h*8 + g;
            float mrow = fmaxf(fmaxf(rm[row*4], rm[row*4+1]),
                               fmaxf(rm[row*4+2], rm[row*4+3]));
            int tc = stg[row] - v0;
            float s = 0.f;
            #pragma unroll
            for (int ni=0; ni<8; ni++){
                float va = c[mi][ni][2*h], vb = c[mi][ni][2*h+1];
                s += __expf(va - mrow) + __expf(vb - mrow);
                int col = wn*64 + ni*8 + 2*tig;
                if (col   == tc) g_tl[m0+row] = va;
                if (col+1 == tc) g_tl[m0+row] = vb;
            }
            s += __shfl_xor_sync(0xffffffffu, s, 1);
            s += __shfl_xor_sync(0xffffffffu, s, 2);
            if (tig == 0) rs[row*4 + wn] = s;
        }
    }
    __syncthreads();
    if (wn == 0 && tig == 0){
        #pragma unroll
        for (int mi=0; mi<4; mi++){
            #pragma unroll
            for (int h=0; h<2; h++){
                int row = wm*64 + mi*16 + h*8 + g;
                float mrow = fmaxf(fmaxf(rm[row*4], rm[row*4+1]),
                                   fmaxf(rm[row*4+2], rm[row*4+3]));
                g_pm[vt*N_ROWS + m0 + row] = mrow;
                g_ps[vt*N_ROWS + m0 + row] = rs[row*4] + rs[row*4+1]
                                           + rs[row*4+2] + rs[row*4+3];
            }
        }
    }
}

// ============================================================
// Kernel 3: split-LSE combine over 125 v-tiles + block partial sums
// ============================================================
__global__ void __launch_bounds__(256) combine_kernel(const int* __restrict__ target){
    int row = blockIdx.x*256 + threadIdx.x;
    float m = -INFINITY;
    for (int i = 0; i < NVT; i++) m = fmaxf(m, g_pm[i*N_ROWS + row]);
    float s = 0.f;
    for (int i = 0; i < NVT; i++) s += g_ps[i*N_ROWS + row] * __expf(g_pm[i*N_ROWS + row] - m);
    float lse = m + logf(s);
    int t = target[row];
    float valid = (t != IGN) ? 1.f : 0.f;
    float loss = (lse - g_tl[row]) * valid;
    float lsev = lse * valid;

    __shared__ float s1[256], s2[256];
    s1[threadIdx.x] = loss;
    s2[threadIdx.x] = lsev;
    __syncthreads();
    for (int off = 128; off > 0; off >>= 1){
        if (threadIdx.x < off){
            s1[threadIdx.x] += s1[threadIdx.x + off];
            s2[threadIdx.x] += s2[threadIdx.x + off];
        }
        __syncthreads();
    }
    if (threadIdx.x == 0){
        g_bp[blockIdx.x*2]   = s1[0];
        g_bp[blockIdx.x*2+1] = s2[0];
    }
}

__global__ void final_kernel(float* __restrict__ out){
    if (threadIdx.x == 0 && blockIdx.x == 0){
        float a = 0.f, b = 0.f;
        for (int i = 0; i < 16; i++){ a += g_bp[2*i]; b += g_bp[2*i+1]; }
        out[0] = a;
        out[1] = b;
    }
}

// ============================================================
extern "C" void kernel_launch(void* const* d_in, const int* in_sizes, int n_in,
                              void* d_out, int out_size){
    const float* x      = (const float*)d_in[0];
    const float* w      = (const float*)d_in[1];
    const int*   target = (const int*)d_in[2];
    float* out = (float*)d_out;

    cudaFuncSetAttribute(gemm_kernel, cudaFuncAttributeMaxDynamicSharedMemorySize, SMEM_BYTES);

    conv_kernel<<<1024, 256>>>((const float4*)x, (const float4*)w);
    dim3 grid(NVT, NRT);
    gemm_kernel<<<grid, 256, SMEM_BYTES>>>(target);
    combine_kernel<<<16, 256>>>(target);
    final_kernel<<<1, 32>>>(out);
}

// round 7
// speedup vs baseline: 1.5065x; 1.0198x over previous
#include <cuda_runtime.h>
#include <cuda_bf16.h>
#include <cuda_fp8.h>
#include <cstdint>
#include <math.h>

#define N_ROWS 4096
#define KDIM   1024
#define VDIM   32000
#define BM 128
#define BN 256
#define BK 64              // fp8 elements per k-chunk
#define NVT (VDIM/BN)      // 125
#define NRT (N_ROWS/BM)    // 32
#define NKT (KDIM/BK)      // 16
#define IGN (-100)
#define WSCL 32.0f
#define IWSCL 0.03125f

// ---- device-global scratch ----
__device__ uint8_t g_X8[N_ROWS*KDIM];    // x e4m3 [n][k], 4 MB
__device__ uint8_t g_W8t[VDIM*KDIM];     // (32*W)^T e4m3 [v][k], 32 MB
__device__ float g_pm[NVT*N_ROWS];
__device__ float g_ps[NVT*N_ROWS];
__device__ float g_tl[N_ROWS];
__device__ float g_bp[32];

// ---- smem: 3-stage A (128 rows x 80B) + 3-stage B (256 rows x 80B) ----
#define APITCH 80
#define BPITCH 80
#define A_ST 10240
#define B_ST 20480
#define A_OFF(s) ((s)*A_ST)
#define B_OFF(s) (30720 + (s)*B_ST)
#define RM_OFF 92160
#define RS_OFF 94208
#define TG_OFF 96256
#define SMEM_BYTES 96768

__device__ __forceinline__ void cp16(uint32_t dst, const void* src){
    asm volatile("cp.async.cg.shared.global [%0], [%1], 16;" :: "r"(dst), "l"(src));
}
__device__ __forceinline__ void cp_commit(){ asm volatile("cp.async.commit_group;"); }

__device__ __forceinline__ uint32_t fp8x4(float a, float b, float c, float d){
    __nv_fp8x2_storage_t lo = __nv_cvt_float2_to_fp8x2(make_float2(a,b), __NV_SATFINITE, __NV_E4M3);
    __nv_fp8x2_storage_t hi = __nv_cvt_float2_to_fp8x2(make_float2(c,d), __NV_SATFINITE, __NV_E4M3);
    return (uint32_t)lo | ((uint32_t)hi << 16);
}

// ============================================================
// Kernel 1a: x fp32 -> e4m3
// ============================================================
__global__ void __launch_bounds__(256) convx_kernel(const float4* __restrict__ x4){
    int idx = blockIdx.x*blockDim.x + threadIdx.x;
    int stride = gridDim.x*blockDim.x;
    uint32_t* xo = reinterpret_cast<uint32_t*>(g_X8);
    const int X4 = N_ROWS*KDIM/4;
    for (int i = idx; i < X4; i += stride){
        float4 v = x4[i];
        xo[i] = fp8x4(v.x, v.y, v.z, v.w);
    }
    if (idx < N_ROWS) g_tl[idx] = 0.f;
}

// ============================================================
// Kernel 1b: W [k][v] fp32 -> (32W)^T [v][k] e4m3, tiled 32v x 64k
// ============================================================
__global__ void __launch_bounds__(256) transw_kernel(const float* __restrict__ w){
    __shared__ float s[32][65];
    const int tid = threadIdx.x;
    const int v0 = blockIdx.x*32, k0 = blockIdx.y*64;
    #pragma unroll
    for (int j = 0; j < 8; j++){
        int idx = tid + j*256;
        int kl = idx >> 5, vl = idx & 31;
        s[vl][kl] = w[(size_t)(k0+kl)*VDIM + v0 + vl];
    }
    __syncthreads();
    #pragma unroll
    for (int j = 0; j < 2; j++){
        int idx = tid + j*256;
        int vl = idx >> 4, kq = idx & 15;
        uint32_t p = fp8x4(s[vl][kq*4]*WSCL, s[vl][kq*4+1]*WSCL,
                           s[vl][kq*4+2]*WSCL, s[vl][kq*4+3]*WSCL);
        reinterpret_cast<uint32_t*>(g_W8t + (size_t)(v0+vl)*KDIM + k0)[kq] = p;
    }
}

// ============================================================
// Kernel 2: 128x256 fp8 GEMM (mma.m16n8k32.e4m3) + fused softmax.
// 16 warps = 4(m) x 4(n), warp tile 32x64. 3-stage cp.async pipeline.
// ============================================================
// A tile: 128 rows x 64B = 512 cp16 (1/thread). B: 256 x 64B = 1024 (2/thread)
#define LOAD_TILES(kt, s) do {                                              \
    int k0_ = (kt)*BK;                                                      \
    { int row_ = tid>>2, seg_ = tid&3;                                      \
      cp16(sbase + A_OFF(s) + (uint32_t)(row_*APITCH + seg_*16),            \
           g_X8 + (size_t)(m0+row_)*KDIM + k0_ + seg_*16); }                \
    _Pragma("unroll")                                                       \
    for (int j_=0; j_<2; j_++){                                             \
        int i_ = tid + j_*512; int row_ = i_>>2, seg_ = i_&3;               \
        cp16(sbase + B_OFF(s) + (uint32_t)(row_*BPITCH + seg_*16),          \
             g_W8t + (size_t)(v0+row_)*KDIM + k0_ + seg_*16); }             \
} while(0)

#define COMPUTE_TILE(s) do {                                                            \
    const int lm_ = lane >> 3, lr_ = lane & 7;                                          \
    _Pragma("unroll")                                                                   \
    for (int kk_=0; kk_<2; kk_++){                                                      \
        uint32_t a_[2][4];                                                              \
        _Pragma("unroll")                                                               \
        for (int mi_=0; mi_<2; mi_++){                                                  \
            int row_ = wm*32 + mi_*16 + (lm_&1)*8 + lr_;                                \
            int koff_ = kk_*32 + (lm_>>1)*16;                                           \
            uint32_t ad_ = sbase + A_OFF(s) + (uint32_t)(row_*APITCH + koff_);          \
            asm volatile("ldmatrix.sync.aligned.m8n8.x4.shared.b16 {%0,%1,%2,%3}, [%4];"\
                : "=r"(a_[mi_][0]),"=r"(a_[mi_][1]),"=r"(a_[mi_][2]),"=r"(a_[mi_][3])   \
                : "r"(ad_));                                                            \
        }                                                                               \
        uint32_t b_[8][2];                                                              \
        _Pragma("unroll")                                                               \
        for (int nq_=0; nq_<4; nq_++){                                                  \
            int row_ = wn*64 + nq_*16 + (lm_>>1)*8 + lr_;                               \
            int koff_ = kk_*32 + (lm_&1)*16;                                            \
            uint32_t bd_ = sbase + B_OFF(s) + (uint32_t)(row_*BPITCH + koff_);          \
            uint32_t t0_,t1_,t2_,t3_;                                                   \
            asm volatile("ldmatrix.sync.aligned.m8n8.x4.shared.b16 {%0,%1,%2,%3}, [%4];"\
                : "=r"(t0_),"=r"(t1_),"=r"(t2_),"=r"(t3_) : "r"(bd_));                  \
            b_[2*nq_][0]=t0_;   b_[2*nq_][1]=t1_;                                       \
            b_[2*nq_+1][0]=t2_; b_[2*nq_+1][1]=t3_;                                     \
        }                                                                               \
        _Pragma("unroll")                                                               \
        for (int mi_=0; mi_<2; mi_++){                                                  \
            _Pragma("unroll")                                                           \
            for (int ni_=0; ni_<8; ni_++){                                              \
                asm volatile("mma.sync.aligned.m16n8k32.row.col.f32.e4m3.e4m3.f32 "     \
                    "{%0,%1,%2,%3}, {%4,%5,%6,%7}, {%8,%9}, {%0,%1,%2,%3};"             \
                    : "+f"(c[mi_][ni_][0]),"+f"(c[mi_][ni_][1]),                        \
                      "+f"(c[mi_][ni_][2]),"+f"(c[mi_][ni_][3])                         \
                    : "r"(a_[mi_][0]),"r"(a_[mi_][1]),"r"(a_[mi_][2]),"r"(a_[mi_][3]),  \
                      "r"(b_[ni_][0]),"r"(b_[ni_][1]));                                 \
            }                                                                           \
        }                                                                               \
    }                                                                                   \
} while(0)

__global__ void __launch_bounds__(512,1) gemm_kernel(const int* __restrict__ target){
    extern __shared__ char smem[];
    const int tid = threadIdx.x, lane = tid & 31, wid = tid >> 5;
    const int wm = wid >> 2, wn = wid & 3;
    const int vt = blockIdx.x, rt = blockIdx.y;
    const int v0 = vt*BN, m0 = rt*BM;

    int* stg = reinterpret_cast<int*>(smem + TG_OFF);
    if (tid < BM) stg[tid] = target[m0 + tid];

    const uint32_t sbase = (uint32_t)__cvta_generic_to_shared(smem);

    float c[2][8][4];
    #pragma unroll
    for (int mi=0; mi<2; mi++)
        #pragma unroll
        for (int ni=0; ni<8; ni++)
            #pragma unroll
            for (int j=0; j<4; j++) c[mi][ni][j] = 0.f;

    LOAD_TILES(0, 0); cp_commit();
    LOAD_TILES(1, 1); cp_commit();
    asm volatile("cp.async.wait_group 1;" ::: "memory");
    __syncthreads();

    #pragma unroll 1
    for (int kt = 0; kt < NKT; kt++){
        COMPUTE_TILE(kt % 3);
        if (kt + 2 < NKT) LOAD_TILES(kt+2, (kt+2) % 3);
        cp_commit();
        asm volatile("cp.async.wait_group 1;" ::: "memory");
        __syncthreads();
    }

    // ---- fused epilogue (values scaled by 32: un-scale before exp) ----
    float* rm = reinterpret_cast<float*>(smem + RM_OFF);  // [128][4]
    float* rs = reinterpret_cast<float*>(smem + RS_OFF);  // [128][4]
    const int g = lane >> 2, tig = lane & 3;

    #pragma unroll
    for (int mi=0; mi<2; mi++){
        #pragma unroll
        for (int h=0; h<2; h++){
            float m = -INFINITY;
            #pragma unroll
            for (int ni=0; ni<8; ni++){
                m = fmaxf(m, c[mi][ni][2*h]);
                m = fmaxf(m, c[mi][ni][2*h+1]);
            }
            m = fmaxf(m, __shfl_xor_sync(0xffffffffu, m, 1));
            m = fmaxf(m, __shfl_xor_sync(0xffffffffu, m, 2));
            int row = wm*32 + mi*16 + h*8 + g;
            if (tig == 0) rm[row*4 + wn] = m * IWSCL;
        }
    }
    __syncthreads();
    #pragma unroll
    for (int mi=0; mi<2; mi++){
        #pragma unroll
        for (int h=0; h<2; h++){
            int row = wm*32 + mi*16 + h*8 + g;
            float mrow = fmaxf(fmaxf(rm[row*4], rm[row*4+1]),
                               fmaxf(rm[row*4+2], rm[row*4+3]));
            int tc = stg[row] - v0;
            float s = 0.f;
            #pragma unroll
            for (int ni=0; ni<8; ni++){
                float va = c[mi][ni][2*h]   * IWSCL;
                float vb = c[mi][ni][2*h+1] * IWSCL;
                s += __expf(va - mrow) + __expf(vb - mrow);
                int col = wn*64 + ni*8 + 2*tig;
                if (col   == tc) g_tl[m0+row] = va;
                if (col+1 == tc) g_tl[m0+row] = vb;
            }
            s += __shfl_xor_sync(0xffffffffu, s, 1);
            s += __shfl_xor_sync(0xffffffffu, s, 2);
            if (tig == 0) rs[row*4 + wn] = s;
        }
    }
    __syncthreads();
    if (wn == 0 && tig == 0){
        #pragma unroll
        for (int mi=0; mi<2; mi++){
            #pragma unroll
            for (int h=0; h<2; h++){
                int row = wm*32 + mi*16 + h*8 + g;
                float mrow = fmaxf(fmaxf(rm[row*4], rm[row*4+1]),
                                   fmaxf(rm[row*4+2], rm[row*4+3]));
                g_pm[vt*N_ROWS + m0 + row] = mrow;
                g_ps[vt*N_ROWS + m0 + row] = rs[row*4] + rs[row*4+1]
                                           + rs[row*4+2] + rs[row*4+3];
            }
        }
    }
}

// ============================================================
// Kernel 3: split-LSE combine + block partial sums
// ============================================================
__global__ void __launch_bounds__(256) combine_kernel(const int* __restrict__ target){
    int row = blockIdx.x*256 + threadIdx.x;
    float m = -INFINITY;
    for (int i = 0; i < NVT; i++) m = fmaxf(m, g_pm[i*N_ROWS + row]);
    float s = 0.f;
    for (int i = 0; i < NVT; i++) s += g_ps[i*N_ROWS + row] * __expf(g_pm[i*N_ROWS + row] - m);
    float lse = m + logf(s);
    int t = target[row];
    float valid = (t != IGN) ? 1.f : 0.f;
    float loss = (lse - g_tl[row]) * valid;
    float lsev = lse * valid;

    __shared__ float s1[256], s2[256];
    s1[threadIdx.x] = loss;
    s2[threadIdx.x] = lsev;
    __syncthreads();
    for (int off = 128; off > 0; off >>= 1){
        if (threadIdx.x < off){
            s1[threadIdx.x] += s1[threadIdx.x + off];
            s2[threadIdx.x] += s2[threadIdx.x + off];
        }
        __syncthreads();
    }
    if (threadIdx.x == 0){
        g_bp[blockIdx.x*2]   = s1[0];
        g_bp[blockIdx.x*2+1] = s2[0];
    }
}

__global__ void final_kernel(float* __restrict__ out){
    if (threadIdx.x == 0 && blockIdx.x == 0){
        float a = 0.f, b = 0.f;
        for (int i = 0; i < 16; i++){ a += g_bp[2*i]; b += g_bp[2*i+1]; }
        out[0] = a;
        out[1] = b;
    }
}

// ============================================================
extern "C" void kernel_launch(void* const* d_in, const int* in_sizes, int n_in,
                              void* d_out, int out_size){
    const float* x      = (const float*)d_in[0];
    const float* w      = (const float*)d_in[1];
    const int*   target = (const int*)d_in[2];
    float* out = (float*)d_out;

    cudaFuncSetAttribute(gemm_kernel, cudaFuncAttributeMaxDynamicSharedMemorySize, SMEM_BYTES);

    convx_kernel<<<256, 256>>>((const float4*)x);
    dim3 tg(VDIM/32, KDIM/64);
    transw_kernel<<<tg, 256>>>(w);
    dim3 grid(NVT, NRT);
    gemm_kernel<<<grid, 512, SMEM_BYTES>>>(target);
    combine_kernel<<<16, 256>>>(target);
    final_kernel<<<1, 32>>>(out);
}

// round 8
// speedup vs baseline: 1.5444x; 1.0252x over previous
#include <cuda_runtime.h>
#include <cuda_bf16.h>
#include <cuda_fp8.h>
#include <cstdint>
#include <math.h>

#define N_ROWS 4096
#define KDIM   1024
#define VDIM   32000
#define BM 128
#define BN 128
#define BK 64              // fp8 elements per k-chunk
#define NVT (VDIM/BN)      // 250
#define NRT (N_ROWS/BM)    // 32
#define NKT (KDIM/BK)      // 16
#define IGN (-100)
#define WSCL 32.0f
#define IWSCL 0.03125f

// ---- device-global scratch ----
__device__ uint8_t g_X8[N_ROWS*KDIM];    // x e4m3 [n][k], 4 MB
__device__ uint8_t g_W8t[VDIM*KDIM];     // (32*W)^T e4m3 [v][k], 32 MB
__device__ float g_pm[NVT*N_ROWS];
__device__ float g_ps[NVT*N_ROWS];
__device__ float g_tl[N_ROWS];
__device__ float g_bp[32];

// ---- smem: 4 stages x (A 128x64B + B 128x64B) = 64KB, + epilogue ----
#define A_ST 8192
#define STG  16384
#define A_OFF(s) ((s)*STG)
#define B_OFF(s) ((s)*STG + A_ST)
#define RM_OFF 65536
#define RS_OFF 66560
#define TG_OFF 67584
#define SMEM_BYTES 68096

// XOR swizzle: row pitch 64B, 4 segs of 16B; seg ^= (row>>1)&3.
// ldmatrix (fixed seg, 8 rows) and cp.async quad stores both conflict-free.
#define SWX(row, seg) ((uint32_t)((row)*64 + ((((seg) ^ (((row)>>1)&3))) << 4)))

__device__ __forceinline__ void cp16(uint32_t dst, const void* src){
    asm volatile("cp.async.cg.shared.global [%0], [%1], 16;" :: "r"(dst), "l"(src));
}
__device__ __forceinline__ void cp_commit(){ asm volatile("cp.async.commit_group;"); }

__device__ __forceinline__ uint32_t fp8x4(float a, float b, float c, float d){
    __nv_fp8x2_storage_t lo = __nv_cvt_float2_to_fp8x2(make_float2(a,b), __NV_SATFINITE, __NV_E4M3);
    __nv_fp8x2_storage_t hi = __nv_cvt_float2_to_fp8x2(make_float2(c,d), __NV_SATFINITE, __NV_E4M3);
    return (uint32_t)lo | ((uint32_t)hi << 16);
}

// ============================================================
// Kernel 1a: x fp32 -> e4m3
// ============================================================
__global__ void __launch_bounds__(256) convx_kernel(const float4* __restrict__ x4){
    int idx = blockIdx.x*blockDim.x + threadIdx.x;
    int stride = gridDim.x*blockDim.x;
    uint32_t* xo = reinterpret_cast<uint32_t*>(g_X8);
    const int X4 = N_ROWS*KDIM/4;
    for (int i = idx; i < X4; i += stride){
        float4 v = x4[i];
        xo[i] = fp8x4(v.x, v.y, v.z, v.w);
    }
    if (idx < N_ROWS) g_tl[idx] = 0.f;
}

// ============================================================
// Kernel 1b: W [k][v] fp32 -> (32W)^T [v][k] e4m3, tiled 32v x 64k
// ============================================================
__global__ void __launch_bounds__(256) transw_kernel(const float* __restrict__ w){
    __shared__ float s[32][65];
    const int tid = threadIdx.x;
    const int v0 = blockIdx.x*32, k0 = blockIdx.y*64;
    #pragma unroll
    for (int j = 0; j < 8; j++){
        int idx = tid + j*256;
        int kl = idx >> 5, vl = idx & 31;
        s[vl][kl] = w[(size_t)(k0+kl)*VDIM + v0 + vl];
    }
    __syncthreads();
    #pragma unroll
    for (int j = 0; j < 2; j++){
        int idx = tid + j*256;
        int vl = idx >> 4, kq = idx & 15;
        uint32_t p = fp8x4(s[vl][kq*4]*WSCL, s[vl][kq*4+1]*WSCL,
                           s[vl][kq*4+2]*WSCL, s[vl][kq*4+3]*WSCL);
        reinterpret_cast<uint32_t*>(g_W8t + (size_t)(v0+vl)*KDIM + k0)[kq] = p;
    }
}

// ============================================================
// Kernel 2: 128x128 fp8 GEMM (mma.m16n8k32.e4m3) + fused softmax.
// 256 threads, 8 warps = 4(m) x 2(n), warp tile 32x64.
// 4-stage cp.async pipeline, 2 CTAs/SM.
// ============================================================
// A tile: 128 rows x 64B = 512 cp16 (2/thread). B same.
#define LOAD_TILES(kt, s) do {                                              \
    int k0_ = (kt)*BK;                                                      \
    _Pragma("unroll")                                                       \
    for (int j_=0; j_<2; j_++){                                             \
        int i_ = tid + j_*256; int row_ = i_>>2, seg_ = i_&3;               \
        cp16(sbase + A_OFF(s) + SWX(row_, seg_),                            \
             g_X8 + (size_t)(m0+row_)*KDIM + k0_ + seg_*16);                \
    }                                                                       \
    _Pragma("unroll")                                                       \
    for (int j_=0; j_<2; j_++){                                             \
        int i_ = tid + j_*256; int row_ = i_>>2, seg_ = i_&3;               \
        cp16(sbase + B_OFF(s) + SWX(row_, seg_),                            \
             g_W8t + (size_t)(v0+row_)*KDIM + k0_ + seg_*16);               \
    }                                                                       \
} while(0)

#define COMPUTE_TILE(s) do {                                                            \
    const int lm_ = lane >> 3, lr_ = lane & 7;                                          \
    _Pragma("unroll")                                                                   \
    for (int kk_=0; kk_<2; kk_++){                                                      \
        uint32_t a_[2][4];                                                              \
        _Pragma("unroll")                                                               \
        for (int mi_=0; mi_<2; mi_++){                                                  \
            int row_ = wm*32 + mi_*16 + (lm_&1)*8 + lr_;                                \
            int seg_ = kk_*2 + (lm_>>1);                                                \
            uint32_t ad_ = sbase + A_OFF(s) + SWX(row_, seg_);                          \
            asm volatile("ldmatrix.sync.aligned.m8n8.x4.shared.b16 {%0,%1,%2,%3}, [%4];"\
                : "=r"(a_[mi_][0]),"=r"(a_[mi_][1]),"=r"(a_[mi_][2]),"=r"(a_[mi_][3])   \
                : "r"(ad_));                                                            \
        }                                                                               \
        uint32_t b_[8][2];                                                              \
        _Pragma("unroll")                                                               \
        for (int nq_=0; nq_<4; nq_++){                                                  \
            int row_ = wn*64 + nq_*16 + (lm_>>1)*8 + lr_;                               \
            int seg_ = kk_*2 + (lm_&1);                                                 \
            uint32_t bd_ = sbase + B_OFF(s) + SWX(row_, seg_);                          \
            uint32_t t0_,t1_,t2_,t3_;                                                   \
            asm volatile("ldmatrix.sync.aligned.m8n8.x4.shared.b16 {%0,%1,%2,%3}, [%4];"\
                : "=r"(t0_),"=r"(t1_),"=r"(t2_),"=r"(t3_) : "r"(bd_));                  \
            b_[2*nq_][0]=t0_;   b_[2*nq_][1]=t1_;                                       \
            b_[2*nq_+1][0]=t2_; b_[2*nq_+1][1]=t3_;                                     \
        }                                                                               \
        _Pragma("unroll")                                                               \
        for (int mi_=0; mi_<2; mi_++){                                                  \
            _Pragma("unroll")                                                           \
            for (int ni_=0; ni_<8; ni_++){                                              \
                asm volatile("mma.sync.aligned.m16n8k32.row.col.f32.e4m3.e4m3.f32 "     \
                    "{%0,%1,%2,%3}, {%4,%5,%6,%7}, {%8,%9}, {%0,%1,%2,%3};"             \
                    : "+f"(c[mi_][ni_][0]),"+f"(c[mi_][ni_][1]),                        \
                      "+f"(c[mi_][ni_][2]),"+f"(c[mi_][ni_][3])                         \
                    : "r"(a_[mi_][0]),"r"(a_[mi_][1]),"r"(a_[mi_][2]),"r"(a_[mi_][3]),  \
                      "r"(b_[ni_][0]),"r"(b_[ni_][1]));                                 \
            }                                                                           \
        }                                                                               \
    }                                                                                   \
} while(0)

__global__ void __launch_bounds__(256,2) gemm_kernel(const int* __restrict__ target){
    extern __shared__ char smem[];
    const int tid = threadIdx.x, lane = tid & 31, wid = tid >> 5;
    const int wm = wid >> 1, wn = wid & 1;
    const int vt = blockIdx.x, rt = blockIdx.y;
    const int v0 = vt*BN, m0 = rt*BM;

    int* stg = reinterpret_cast<int*>(smem + TG_OFF);
    if (tid < BM) stg[tid] = target[m0 + tid];

    const uint32_t sbase = (uint32_t)__cvta_generic_to_shared(smem);

    float c[2][8][4];
    #pragma unroll
    for (int mi=0; mi<2; mi++)
        #pragma unroll
        for (int ni=0; ni<8; ni++)
            #pragma unroll
            for (int j=0; j<4; j++) c[mi][ni][j] = 0.f;

    LOAD_TILES(0, 0); cp_commit();
    LOAD_TILES(1, 1); cp_commit();
    LOAD_TILES(2, 2); cp_commit();
    asm volatile("cp.async.wait_group 2;" ::: "memory");
    __syncthreads();

    #pragma unroll 1
    for (int kt = 0; kt < NKT; kt++){
        COMPUTE_TILE(kt & 3);
        if (kt + 3 < NKT) LOAD_TILES(kt+3, (kt+3) & 3);
        cp_commit();
        asm volatile("cp.async.wait_group 2;" ::: "memory");
        __syncthreads();
    }

    // ---- fused epilogue (values scaled by 32: un-scale before exp) ----
    float* rm = reinterpret_cast<float*>(smem + RM_OFF);  // [128][2]
    float* rs = reinterpret_cast<float*>(smem + RS_OFF);  // [128][2]
    const int g = lane >> 2, tig = lane & 3;

    #pragma unroll
    for (int mi=0; mi<2; mi++){
        #pragma unroll
        for (int h=0; h<2; h++){
            float m = -INFINITY;
            #pragma unroll
            for (int ni=0; ni<8; ni++){
                m = fmaxf(m, c[mi][ni][2*h]);
                m = fmaxf(m, c[mi][ni][2*h+1]);
            }
            m = fmaxf(m, __shfl_xor_sync(0xffffffffu, m, 1));
            m = fmaxf(m, __shfl_xor_sync(0xffffffffu, m, 2));
            int row = wm*32 + mi*16 + h*8 + g;
            if (tig == 0) rm[row*2 + wn] = m * IWSCL;
        }
    }
    __syncthreads();
    #pragma unroll
    for (int mi=0; mi<2; mi++){
        #pragma unroll
        for (int h=0; h<2; h++){
            int row = wm*32 + mi*16 + h*8 + g;
            float mrow = fmaxf(rm[row*2], rm[row*2+1]);
            int tc = stg[row] - v0;
            float s = 0.f;
            #pragma unroll
            for (int ni=0; ni<8; ni++){
                float va = c[mi][ni][2*h]   * IWSCL;
                float vb = c[mi][ni][2*h+1] * IWSCL;
                s += __expf(va - mrow) + __expf(vb - mrow);
                int col = wn*64 + ni*8 + 2*tig;
                if (col   == tc) g_tl[m0+row] = va;
                if (col+1 == tc) g_tl[m0+row] = vb;
            }
            s += __shfl_xor_sync(0xffffffffu, s, 1);
            s += __shfl_xor_sync(0xffffffffu, s, 2);
            if (tig == 0) rs[row*2 + wn] = s;
        }
    }
    __syncthreads();
    if (wn == 0 && tig == 0){
        #pragma unroll
        for (int mi=0; mi<2; mi++){
            #pragma unroll
            for (int h=0; h<2; h++){
                int row = wm*32 + mi*16 + h*8 + g;
                g_pm[vt*N_ROWS + m0 + row] = fmaxf(rm[row*2], rm[row*2+1]);
                g_ps[vt*N_ROWS + m0 + row] = rs[row*2] + rs[row*2+1];
            }
        }
    }
}

// ============================================================
// Kernel 3: single-pass online split-LSE combine + block partials
// ============================================================
__global__ void __launch_bounds__(256) combine_kernel(const int* __restrict__ target){
    int row = blockIdx.x*256 + threadIdx.x;
    float m = -INFINITY, s = 0.f;
    #pragma unroll 4
    for (int i = 0; i < NVT; i++){
        float pm = g_pm[i*N_ROWS + row];
        float ps = g_ps[i*N_ROWS + row];
        float mn = fmaxf(m, pm);
        s = s*__expf(m - mn) + ps*__expf(pm - mn);
        m = mn;
    }
    float lse = m + logf(s);
    int t = target[row];
    float valid = (t != IGN) ? 1.f : 0.f;
    float loss = (lse - g_tl[row]) * valid;
    float lsev = lse * valid;

    __shared__ float s1[256], s2[256];
    s1[threadIdx.x] = loss;
    s2[threadIdx.x] = lsev;
    __syncthreads();
    for (int off = 128; off > 0; off >>= 1){
        if (threadIdx.x < off){
            s1[threadIdx.x] += s1[threadIdx.x + off];
            s2[threadIdx.x] += s2[threadIdx.x + off];
        }
        __syncthreads();
    }
    if (threadIdx.x == 0){
        g_bp[blockIdx.x*2]   = s1[0];
        g_bp[blockIdx.x*2+1] = s2[0];
    }
}

__global__ void final_kernel(float* __restrict__ out){
    if (threadIdx.x == 0 && blockIdx.x == 0){
        float a = 0.f, b = 0.f;
        for (int i = 0; i < 16; i++){ a += g_bp[2*i]; b += g_bp[2*i+1]; }
        out[0] = a;
        out[1] = b;
    }
}

// ============================================================
extern "C" void kernel_launch(void* const* d_in, const int* in_sizes, int n_in,
                              void* d_out, int out_size){
    const float* x      = (const float*)d_in[0];
    const float* w      = (const float*)d_in[1];
    const int*   target = (const int*)d_in[2];
    float* out = (float*)d_out;

    cudaFuncSetAttribute(gemm_kernel, cudaFuncAttributeMaxDynamicSharedMemorySize, SMEM_BYTES);

    convx_kernel<<<256, 256>>>((const float4*)x);
    dim3 tg(VDIM/32, KDIM/64);
    transw_kernel<<<tg, 256>>>(w);
    dim3 grid(NVT, NRT);
    gemm_kernel<<<grid, 256, SMEM_BYTES>>>(target);
    combine_kernel<<<16, 256>>>(target);
    final_kernel<<<1, 32>>>(out);
}